// round 3
// baseline (speedup 1.0000x reference)
#include <cuda_runtime.h>

// HDTBLUT: 4 LUT kernels (h,d,t,b) x 4 rotations, 2x upscale, reflect pad.
// R3: pack nibble words straight from global (no staging tile), 2 px/thread
// so the 7 packed-row loads amortize over 2 pixels. Kernel is L1tex
// wavefront bound; 512 gather wavefronts/warp/32px are the floor.

#define NN    1024
#define OW    2048
#define TXW   64          // tile width in pixels (32 threads x 2 px)
#define TY    8
#define PW    10          // packed words per row (covers [x0-8, x0+72))
#define SROWS 14          // TY + 6

__device__ __forceinline__ void addx2(unsigned long long &a, unsigned long long b) {
    asm("add.rn.f32x2 %0, %0, %1;" : "+l"(a) : "l"(b));
}
__device__ __forceinline__ float lo32(unsigned long long s) {
    return __uint_as_float((unsigned int)s);
}
__device__ __forceinline__ float hi32(unsigned long long s) {
    return __uint_as_float((unsigned int)(s >> 32));
}
__device__ __forceinline__ unsigned rev16(unsigned w) {
    unsigned s = ((w & 0x0F0Fu) << 4) | ((w >> 4) & 0x0F0Fu);
    return ((s & 0xFFu) << 8) | (s >> 8);
}
__device__ __forceinline__ int refl(int c) {
    return c < 0 ? -c : (c >= NN ? 2 * NN - 2 - c : c);
}

// Compute the combined 2x2 output block for one pixel.
// Q[r] holds 16 big-endian nibbles; window nibble j (x-offset j-3 from the
// pixel, rows r-3) of pixel PX sits at bits [60-4*(j+PX), 64-4*(j+PX)).
template <int PX>
__device__ __forceinline__ float4 pixel_block(
    const unsigned long long* __restrict__ Q,
    const ulonglong2* __restrict__ wh, const ulonglong2* __restrict__ wd,
    const ulonglong2* __restrict__ wt, const ulonglong2* __restrict__ wb)
{
#define NIB(r, j) ((unsigned)(Q[r] >> (60 - 4 * ((j) + PX))) & 0xFu)

    const unsigned iH0 = (unsigned)(Q[3] >> (36 - 4 * PX)) & 0xFFFFu;
    const unsigned wl  = (unsigned)(Q[3] >> (48 - 4 * PX)) & 0xFFFFu;
    const unsigned iH2 = rev16(wl);
    const unsigned A12 = (wl & 0xFu) << 12;   // center pixel << 12

    const unsigned iH1 = A12 | (NIB(4,3) << 8) | (NIB(5,3) << 4) | NIB(6,3);
    const unsigned iH3 = A12 | (NIB(2,3) << 8) | (NIB(1,3) << 4) | NIB(0,3);

    const unsigned iD0 = A12 | (NIB(4,4) << 8) | (NIB(5,5) << 4) | NIB(6,6);
    const unsigned iD1 = A12 | (NIB(4,2) << 8) | (NIB(5,1) << 4) | NIB(6,0);
    const unsigned iD2 = A12 | (NIB(2,2) << 8) | (NIB(1,1) << 4) | NIB(0,0);
    const unsigned iD3 = A12 | (NIB(2,4) << 8) | (NIB(1,5) << 4) | NIB(0,6);

    const unsigned iT0 = A12 | (NIB(5,4) << 8) | (NIB(6,4) << 4) | NIB(6,5);
    const unsigned iT1 = A12 | (NIB(4,1) << 8) | (NIB(4,0) << 4) | NIB(5,0);
    const unsigned iT2 = A12 | (NIB(1,2) << 8) | (NIB(0,2) << 4) | NIB(0,1);
    const unsigned iT3 = A12 | (NIB(2,5) << 8) | (NIB(2,6) << 4) | NIB(1,6);

    const unsigned iB0 = A12 | (NIB(4,5) << 8) | (NIB(4,6) << 4) | NIB(5,6);
    const unsigned iB1 = A12 | (NIB(5,2) << 8) | (NIB(6,2) << 4) | NIB(6,1);
    const unsigned iB2 = A12 | (NIB(2,1) << 8) | (NIB(2,0) << 4) | NIB(1,0);
    const unsigned iB3 = A12 | (NIB(1,4) << 8) | (NIB(0,4) << 4) | NIB(0,5);
#undef NIB

    unsigned long long s0l = 0, s0h = 0, s1l = 0, s1h = 0;
    unsigned long long s2l = 0, s2h = 0, s3l = 0, s3h = 0;

#define PASS(W, I0, I1, I2, I3) { ulonglong2 g; \
    g = __ldg(&W[I0]); addx2(s0l, g.x); addx2(s0h, g.y); \
    g = __ldg(&W[I1]); addx2(s1l, g.x); addx2(s1h, g.y); \
    g = __ldg(&W[I2]); addx2(s2l, g.x); addx2(s2h, g.y); \
    g = __ldg(&W[I3]); addx2(s3l, g.x); addx2(s3h, g.y); }

    PASS(wh, iH0, iH1, iH2, iH3)
    PASS(wd, iD0, iD1, iD2, iD3)
    PASS(wt, iT0, iT1, iT2, iT3)
    PASS(wb, iB0, iB1, iB2, iB3)
#undef PASS

    const float S0x = lo32(s0l), S0y = hi32(s0l), S0z = lo32(s0h), S0w = hi32(s0h);
    const float S1x = lo32(s1l), S1y = hi32(s1l), S1z = lo32(s1h), S1w = hi32(s1h);
    const float S2x = lo32(s2l), S2y = hi32(s2l), S2z = lo32(s2h), S2w = hi32(s2h);
    const float S3x = lo32(s3l), S3y = hi32(s3l), S3z = lo32(s3h), S3w = hi32(s3h);

    // Inverse-rotation permutation of the 2x2 block, then /4
    return make_float4((S0x + S1z + S2w + S3y) * 0.25f,
                       (S0y + S1x + S2z + S3w) * 0.25f,
                       (S0z + S1w + S2y + S3x) * 0.25f,
                       (S0w + S1y + S2x + S3z) * 0.25f);
}

__global__ __launch_bounds__(256)
void lut4_kernel(const int* __restrict__ img,
                 const ulonglong2* __restrict__ wh,
                 const ulonglong2* __restrict__ wd,
                 const ulonglong2* __restrict__ wt,
                 const ulonglong2* __restrict__ wb,
                 float* __restrict__ out)
{
    __shared__ unsigned int pk[SROWS * PW];

    const int tx = threadIdx.x, ty = threadIdx.y;
    const int tid = ty * 32 + tx;
    const int x0 = blockIdx.x * TXW, y0 = blockIdx.y * TY;
    const int* ib = img + (size_t)blockIdx.z * (NN * NN);

    // Pack straight from global: word w of row r covers image columns
    // [x0-8+8w, x0+8w), big-endian nibbles. Interior-x blocks use two
    // aligned 16B loads; edge blocks reflect per element.
    if (tid < SROWS * PW) {
        const int row = tid / PW, w = tid - row * PW;
        const int gy = refl(y0 - 3 + row);
        const int gx0 = x0 - 8 + 8 * w;
        unsigned word;
        if (x0 >= 8 && x0 + 72 <= NN) {
            const int4* s = (const int4*)(ib + gy * NN + gx0);
            const int4 u0 = __ldg(s), u1 = __ldg(s + 1);
            word = ((unsigned)u0.x << 28) | ((unsigned)u0.y << 24) |
                   ((unsigned)u0.z << 20) | ((unsigned)u0.w << 16) |
                   ((unsigned)u1.x << 12) | ((unsigned)u1.y << 8)  |
                   ((unsigned)u1.z << 4)  |  (unsigned)u1.w;
        } else {
            word = 0;
            const int* rp = ib + gy * NN;
#pragma unroll
            for (int k = 0; k < 8; k++)
                word = (word << 4) | (unsigned)__ldg(rp + refl(gx0 + k));
        }
        pk[tid] = word;
    }
    __syncthreads();

    // Load 7 window rows as pre-shifted 64-bit registers covering both
    // of this thread's pixels (LR columns x0+2tx and x0+2tx+1).
    // Packed nibble position of pixel-0's leftmost tap (col-3) is 2tx+5.
    unsigned long long Q[7];
    const int base = 2 * tx + 5;
    const int w0 = base >> 3;
    const int sh = (base & 7) * 4;
#pragma unroll
    for (int r = 0; r < 7; r++) {
        const unsigned* rw = &pk[(ty + r) * PW + w0];
        Q[r] = (((unsigned long long)rw[0] << 32) | rw[1]) << sh;
    }

    const float4 p0 = pixel_block<0>(Q, wh, wd, wt, wb);
    const float4 p1 = pixel_block<1>(Q, wh, wd, wt, wb);

    float* ob = out + (size_t)blockIdx.z * ((size_t)OW * OW)
                    + (size_t)(2 * (y0 + ty)) * OW + 2 * (x0 + 2 * tx);
    *(float4*)(ob)      = make_float4(p0.x, p0.y, p1.x, p1.y);
    *(float4*)(ob + OW) = make_float4(p0.z, p0.w, p1.z, p1.w);
}

extern "C" void kernel_launch(void* const* d_in, const int* in_sizes, int n_in,
                              void* d_out, int out_size) {
    (void)n_in; (void)out_size;
    const int* img = (const int*)d_in[0];
    const int B = in_sizes[0] / (NN * NN);
    dim3 blk(32, TY, 1);
    dim3 grd(NN / TXW, NN / TY, B);
    lut4_kernel<<<grd, blk>>>(img,
                              (const ulonglong2*)d_in[1],
                              (const ulonglong2*)d_in[2],
                              (const ulonglong2*)d_in[3],
                              (const ulonglong2*)d_in[4],
                              (float*)d_out);
}

// round 4
// speedup vs baseline: 1.0474x; 1.0474x over previous
#include <cuda_runtime.h>

// HDTBLUT: 4 LUT kernels (h,d,t,b) x 4 rotations, 2x upscale, reflect pad.
// R4 = R2 structure (1 px/thread, best so far) + direct-from-global nibble
// packing (no staging tile, one barrier). Kernel is L1tex wavefront bound;
// the 16 random LDG.128 gathers per thread are the floor.

#define NN    1024
#define OW    2048
#define TX    32
#define TY    8
#define PW    8           // padded words per packed row (6 used)
#define SROWS 14          // TY + 6

__device__ __forceinline__ void addx2(unsigned long long &a, unsigned long long b) {
    asm("add.rn.f32x2 %0, %0, %1;" : "+l"(a) : "l"(b));
}
__device__ __forceinline__ float lo32(unsigned long long s) {
    return __uint_as_float((unsigned int)s);
}
__device__ __forceinline__ float hi32(unsigned long long s) {
    return __uint_as_float((unsigned int)(s >> 32));
}
// nibble-reverse a 16-bit value: n0n1n2n3 -> n3n2n1n0
__device__ __forceinline__ unsigned rev16(unsigned w) {
    unsigned s = ((w & 0x0F0Fu) << 4) | ((w >> 4) & 0x0F0Fu);
    return ((s & 0xFFu) << 8) | (s >> 8);
}
__device__ __forceinline__ int refl(int c) {
    return c < 0 ? -c : (c >= NN ? 2 * NN - 2 - c : c);
}

__global__ __launch_bounds__(256)
void lut4_kernel(const int* __restrict__ img,
                 const ulonglong2* __restrict__ wh,
                 const ulonglong2* __restrict__ wd,
                 const ulonglong2* __restrict__ wt,
                 const ulonglong2* __restrict__ wb,
                 float* __restrict__ out)
{
    __shared__ unsigned int pk[SROWS * PW];

    const int tx = threadIdx.x, ty = threadIdx.y;
    const int tid = ty * TX + tx;
    const int x0 = blockIdx.x * TX, y0 = blockIdx.y * TY;
    const int* ib = img + (size_t)blockIdx.z * (NN * NN);

    // Pack straight from global: word w of row r covers image columns
    // [x0-8+8w, x0+8w), big-endian nibbles. Interior-x blocks use two
    // aligned 16B loads; edge block-columns reflect per element.
    if (tid < SROWS * 6) {
        const int row = tid / 6, w = tid - row * 6;
        const int gy = refl(y0 - 3 + row);
        const int gx0 = x0 - 8 + 8 * w;
        unsigned word;
        if (x0 >= 8 && x0 + 40 <= NN) {
            const int4* s = (const int4*)(ib + gy * NN + gx0);
            const int4 u0 = __ldg(s), u1 = __ldg(s + 1);
            word = ((unsigned)u0.x << 28) | ((unsigned)u0.y << 24) |
                   ((unsigned)u0.z << 20) | ((unsigned)u0.w << 16) |
                   ((unsigned)u1.x << 12) | ((unsigned)u1.y << 8)  |
                   ((unsigned)u1.z << 4)  |  (unsigned)u1.w;
        } else {
            word = 0;
            const int* rp = ib + gy * NN;
#pragma unroll
            for (int k = 0; k < 8; k++)
                word = (word << 4) | (unsigned)__ldg(rp + refl(gx0 + k));
        }
        pk[row * PW + w] = word;
    }
    __syncthreads();

    // Load 7 window rows as pre-shifted 64-bit registers.
    // Pixel (x0+tx); leftmost tap col x0+tx-3 is packed nibble tx+5.
    // After the shift, window nibble j (j=0..6; center j=3) sits at
    // bits [60-4j, 64-4j).
    unsigned long long Q[7];
    const int base = tx + 5;
    const int w0 = base >> 3;
    const int sh = (base & 7) * 4;
#pragma unroll
    for (int r = 0; r < 7; r++) {
        const unsigned* rw = &pk[(ty + r) * PW + w0];
        Q[r] = (((unsigned long long)rw[0] << 32) | rw[1]) << sh;
    }

#define NIB(r, j) ((unsigned)(Q[r] >> (60 - 4 * (j))) & 0xFu)

    // h rotation 0: nibbles j=3..6 of center row, directly.
    const unsigned iH0 = (unsigned)(Q[3] >> 36) & 0xFFFFu;
    // left window (j=0..3): v(x-3)<<12|v(x-2)<<8|v(x-1)<<4|v(x)
    const unsigned wl  = (unsigned)(Q[3] >> 48) & 0xFFFFu;
    const unsigned iH2 = rev16(wl);
    const unsigned A12 = (wl & 0xFu) << 12;   // center pixel << 12

    const unsigned iH1 = A12 | (NIB(4,3) << 8) | (NIB(5,3) << 4) | NIB(6,3);
    const unsigned iH3 = A12 | (NIB(2,3) << 8) | (NIB(1,3) << 4) | NIB(0,3);

    const unsigned iD0 = A12 | (NIB(4,4) << 8) | (NIB(5,5) << 4) | NIB(6,6);
    const unsigned iD1 = A12 | (NIB(4,2) << 8) | (NIB(5,1) << 4) | NIB(6,0);
    const unsigned iD2 = A12 | (NIB(2,2) << 8) | (NIB(1,1) << 4) | NIB(0,0);
    const unsigned iD3 = A12 | (NIB(2,4) << 8) | (NIB(1,5) << 4) | NIB(0,6);

    const unsigned iT0 = A12 | (NIB(5,4) << 8) | (NIB(6,4) << 4) | NIB(6,5);
    const unsigned iT1 = A12 | (NIB(4,1) << 8) | (NIB(4,0) << 4) | NIB(5,0);
    const unsigned iT2 = A12 | (NIB(1,2) << 8) | (NIB(0,2) << 4) | NIB(0,1);
    const unsigned iT3 = A12 | (NIB(2,5) << 8) | (NIB(2,6) << 4) | NIB(1,6);

    const unsigned iB0 = A12 | (NIB(4,5) << 8) | (NIB(4,6) << 4) | NIB(5,6);
    const unsigned iB1 = A12 | (NIB(5,2) << 8) | (NIB(6,2) << 4) | NIB(6,1);
    const unsigned iB2 = A12 | (NIB(2,1) << 8) | (NIB(2,0) << 4) | NIB(1,0);
    const unsigned iB3 = A12 | (NIB(1,4) << 8) | (NIB(0,4) << 4) | NIB(0,5);

#undef NIB

    // Per-rotation packed accumulators: (w0,w1) in *l, (w2,w3) in *h
    unsigned long long s0l = 0, s0h = 0, s1l = 0, s1h = 0;
    unsigned long long s2l = 0, s2h = 0, s3l = 0, s3h = 0;

#define PASS(W, I0, I1, I2, I3) { ulonglong2 g; \
    g = __ldg(&W[I0]); addx2(s0l, g.x); addx2(s0h, g.y); \
    g = __ldg(&W[I1]); addx2(s1l, g.x); addx2(s1h, g.y); \
    g = __ldg(&W[I2]); addx2(s2l, g.x); addx2(s2h, g.y); \
    g = __ldg(&W[I3]); addx2(s3l, g.x); addx2(s3h, g.y); }

    PASS(wh, iH0, iH1, iH2, iH3)
    PASS(wd, iD0, iD1, iD2, iD3)
    PASS(wt, iT0, iT1, iT2, iT3)
    PASS(wb, iB0, iB1, iB2, iB3)
#undef PASS

    const float S0x = lo32(s0l), S0y = hi32(s0l), S0z = lo32(s0h), S0w = hi32(s0h);
    const float S1x = lo32(s1l), S1y = hi32(s1l), S1z = lo32(s1h), S1w = hi32(s1h);
    const float S2x = lo32(s2l), S2y = hi32(s2l), S2z = lo32(s2h), S2w = hi32(s2h);
    const float S3x = lo32(s3l), S3y = hi32(s3l), S3z = lo32(s3h), S3w = hi32(s3h);

    // Inverse-rotation permutation of the 2x2 block, then /4
    const float a00 = (S0x + S1z + S2w + S3y) * 0.25f;
    const float a01 = (S0y + S1x + S2z + S3w) * 0.25f;
    const float a10 = (S0z + S1w + S2y + S3x) * 0.25f;
    const float a11 = (S0w + S1y + S2x + S3z) * 0.25f;

    float* ob = out + (size_t)blockIdx.z * ((size_t)OW * OW)
                    + (size_t)(2 * (y0 + ty)) * OW + 2 * (x0 + tx);
    *(float2*)(ob)      = make_float2(a00, a01);
    *(float2*)(ob + OW) = make_float2(a10, a11);
}

extern "C" void kernel_launch(void* const* d_in, const int* in_sizes, int n_in,
                              void* d_out, int out_size) {
    (void)n_in; (void)out_size;
    const int* img = (const int*)d_in[0];
    const int B = in_sizes[0] / (NN * NN);
    dim3 blk(TX, TY, 1);
    dim3 grd(NN / TX, NN / TY, B);
    lut4_kernel<<<grd, blk>>>(img,
                              (const ulonglong2*)d_in[1],
                              (const ulonglong2*)d_in[2],
                              (const ulonglong2*)d_in[3],
                              (const ulonglong2*)d_in[4],
                              (float*)d_out);
}

// round 5
// speedup vs baseline: 1.0486x; 1.0011x over previous
#include <cuda_runtime.h>

// HDTBLUT: 4 LUT kernels (h,d,t,b) x 4 rotations, 2x upscale, reflect pad.
// R5 = R4 + 32-bit window rows (all taps live in the high word of the
// shifted row) + aligned LDS.64 pair loads + occupancy 7 CTA/SM.
// Kernel is L1tex wavefront bound; 16 random LDG.128 gathers/thread = floor.

#define NN    1024
#define OW    2048
#define TX    32
#define TY    8
#define PR    6           // packed 64-bit pair entries per row (5 used + pad)
#define SROWS 14          // TY + 6

__device__ __forceinline__ void addx2(unsigned long long &a, unsigned long long b) {
    asm("add.rn.f32x2 %0, %0, %1;" : "+l"(a) : "l"(b));
}
__device__ __forceinline__ float lo32(unsigned long long s) {
    return __uint_as_float((unsigned int)s);
}
__device__ __forceinline__ float hi32(unsigned long long s) {
    return __uint_as_float((unsigned int)(s >> 32));
}
// nibble-reverse a 16-bit value: n0n1n2n3 -> n3n2n1n0
__device__ __forceinline__ unsigned rev16(unsigned w) {
    unsigned s = ((w & 0x0F0Fu) << 4) | ((w >> 4) & 0x0F0Fu);
    return ((s & 0xFFu) << 8) | (s >> 8);
}
__device__ __forceinline__ int refl(int c) {
    return c < 0 ? -c : (c >= NN ? 2 * NN - 2 - c : c);
}

__global__ __launch_bounds__(256, 7)
void lut4_kernel(const int* __restrict__ img,
                 const ulonglong2* __restrict__ wh,
                 const ulonglong2* __restrict__ wd,
                 const ulonglong2* __restrict__ wt,
                 const ulonglong2* __restrict__ wb,
                 float* __restrict__ out)
{
    // pk64[row][w] = (word[w] : word[w+1]); 8B-aligned pair loads.
    __shared__ unsigned long long pk64[SROWS * PR];

    const int tx = threadIdx.x, ty = threadIdx.y;
    const int tid = ty * TX + tx;
    const int x0 = blockIdx.x * TX, y0 = blockIdx.y * TY;
    const int* ib = img + (size_t)blockIdx.z * (NN * NN);

    // Pack straight from global: word w of row r covers image columns
    // [x0-8+8w, x0+8w), big-endian nibbles. Interior-x blocks use two
    // aligned 16B loads; edge block-columns reflect per element.
    // Word w is mirrored into pk64[row][w].hi and pk64[row][w-1].lo.
    if (tid < SROWS * 6) {
        const int row = tid / 6, w = tid - row * 6;
        const int gy = refl(y0 - 3 + row);
        const int gx0 = x0 - 8 + 8 * w;
        unsigned word;
        if (x0 >= 8 && x0 + 40 <= NN) {
            const int4* s = (const int4*)(ib + gy * NN + gx0);
            const int4 u0 = __ldg(s), u1 = __ldg(s + 1);
            word = ((unsigned)u0.x << 28) | ((unsigned)u0.y << 24) |
                   ((unsigned)u0.z << 20) | ((unsigned)u0.w << 16) |
                   ((unsigned)u1.x << 12) | ((unsigned)u1.y << 8)  |
                   ((unsigned)u1.z << 4)  |  (unsigned)u1.w;
        } else {
            word = 0;
            const int* rp = ib + gy * NN;
#pragma unroll
            for (int k = 0; k < 8; k++)
                word = (word << 4) | (unsigned)__ldg(rp + refl(gx0 + k));
        }
        unsigned* pw = (unsigned*)&pk64[row * PR];
        if (w < 5) pw[2 * w + 1] = word;          // high half of entry w
        if (w > 0) pw[2 * (w - 1)] = word;        // low  half of entry w-1
    }
    __syncthreads();

    // Window rows as 32-bit regs: H[r] = top 32 bits of (word[w0]:word[w0+1])<<sh.
    // Window nibble j (j=0..6; center j=3) sits at bits [28-4j, 32-4j).
    unsigned H[7];
    const int base = tx + 5;
    const int w0 = base >> 3;
    const int sh = (base & 7) * 4;
#pragma unroll
    for (int r = 0; r < 7; r++) {
        const unsigned long long P = pk64[(ty + r) * PR + w0];
        H[r] = __funnelshift_l((unsigned)P, (unsigned)(P >> 32), sh);
    }

#define NIB(r, j) ((H[r] >> (28 - 4 * (j))) & 0xFu)

    // h rotation 0: nibbles j=3..6 of center row, directly.
    const unsigned iH0 = (H[3] >> 4) & 0xFFFFu;
    // left window (j=0..3): v(x-3)<<12|v(x-2)<<8|v(x-1)<<4|v(x)
    const unsigned wl  = H[3] >> 16;
    const unsigned iH2 = rev16(wl);
    const unsigned A12 = (wl & 0xFu) << 12;   // center pixel << 12

    const unsigned iH1 = A12 | (NIB(4,3) << 8) | (NIB(5,3) << 4) | NIB(6,3);
    const unsigned iH3 = A12 | (NIB(2,3) << 8) | (NIB(1,3) << 4) | NIB(0,3);

    const unsigned iD0 = A12 | (NIB(4,4) << 8) | (NIB(5,5) << 4) | NIB(6,6);
    const unsigned iD1 = A12 | (NIB(4,2) << 8) | (NIB(5,1) << 4) | NIB(6,0);
    const unsigned iD2 = A12 | (NIB(2,2) << 8) | (NIB(1,1) << 4) | NIB(0,0);
    const unsigned iD3 = A12 | (NIB(2,4) << 8) | (NIB(1,5) << 4) | NIB(0,6);

    const unsigned iT0 = A12 | (NIB(5,4) << 8) | (NIB(6,4) << 4) | NIB(6,5);
    const unsigned iT1 = A12 | (NIB(4,1) << 8) | (NIB(4,0) << 4) | NIB(5,0);
    const unsigned iT2 = A12 | (NIB(1,2) << 8) | (NIB(0,2) << 4) | NIB(0,1);
    const unsigned iT3 = A12 | (NIB(2,5) << 8) | (NIB(2,6) << 4) | NIB(1,6);

    const unsigned iB0 = A12 | (NIB(4,5) << 8) | (NIB(4,6) << 4) | NIB(5,6);
    const unsigned iB1 = A12 | (NIB(5,2) << 8) | (NIB(6,2) << 4) | NIB(6,1);
    const unsigned iB2 = A12 | (NIB(2,1) << 8) | (NIB(2,0) << 4) | NIB(1,0);
    const unsigned iB3 = A12 | (NIB(1,4) << 8) | (NIB(0,4) << 4) | NIB(0,5);

#undef NIB

    // Per-rotation packed accumulators: (w0,w1) in *l, (w2,w3) in *h
    unsigned long long s0l = 0, s0h = 0, s1l = 0, s1h = 0;
    unsigned long long s2l = 0, s2h = 0, s3l = 0, s3h = 0;

#define PASS(W, I0, I1, I2, I3) { ulonglong2 g; \
    g = __ldg(&W[I0]); addx2(s0l, g.x); addx2(s0h, g.y); \
    g = __ldg(&W[I1]); addx2(s1l, g.x); addx2(s1h, g.y); \
    g = __ldg(&W[I2]); addx2(s2l, g.x); addx2(s2h, g.y); \
    g = __ldg(&W[I3]); addx2(s3l, g.x); addx2(s3h, g.y); }

    PASS(wh, iH0, iH1, iH2, iH3)
    PASS(wd, iD0, iD1, iD2, iD3)
    PASS(wt, iT0, iT1, iT2, iT3)
    PASS(wb, iB0, iB1, iB2, iB3)
#undef PASS

    const float S0x = lo32(s0l), S0y = hi32(s0l), S0z = lo32(s0h), S0w = hi32(s0h);
    const float S1x = lo32(s1l), S1y = hi32(s1l), S1z = lo32(s1h), S1w = hi32(s1h);
    const float S2x = lo32(s2l), S2y = hi32(s2l), S2z = lo32(s2h), S2w = hi32(s2h);
    const float S3x = lo32(s3l), S3y = hi32(s3l), S3z = lo32(s3h), S3w = hi32(s3h);

    // Inverse-rotation permutation of the 2x2 block, then /4
    const float a00 = (S0x + S1z + S2w + S3y) * 0.25f;
    const float a01 = (S0y + S1x + S2z + S3w) * 0.25f;
    const float a10 = (S0z + S1w + S2y + S3x) * 0.25f;
    const float a11 = (S0w + S1y + S2x + S3z) * 0.25f;

    float* ob = out + (size_t)blockIdx.z * ((size_t)OW * OW)
                    + (size_t)(2 * (y0 + ty)) * OW + 2 * (x0 + tx);
    *(float2*)(ob)      = make_float2(a00, a01);
    *(float2*)(ob + OW) = make_float2(a10, a11);
}

extern "C" void kernel_launch(void* const* d_in, const int* in_sizes, int n_in,
                              void* d_out, int out_size) {
    (void)n_in; (void)out_size;
    const int* img = (const int*)d_in[0];
    const int B = in_sizes[0] / (NN * NN);
    dim3 blk(TX, TY, 1);
    dim3 grd(NN / TX, NN / TY, B);
    lut4_kernel<<<grd, blk>>>(img,
                              (const ulonglong2*)d_in[1],
                              (const ulonglong2*)d_in[2],
                              (const ulonglong2*)d_in[3],
                              (const ulonglong2*)d_in[4],
                              (float*)d_out);
}